// round 2
// baseline (speedup 1.0000x reference)
#include <cuda_runtime.h>
#include <math.h>

#define NFFT 16000
#define DIN  2048
#define BATCH 1024
#define OUTN 3000
#define TPB  512

// 64 MB scratch for z (device global: allowed; no runtime allocation)
__device__ float g_z[BATCH * (size_t)NFFT];

__device__ __forceinline__ int rev7(int x) { return (int)(__brev((unsigned)x) >> 25); }
__device__ __forceinline__ int rev5(int n) {
    int d0 = n % 5; n /= 5; int d1 = n % 5; int d2 = n / 5;
    return d0 * 25 + d1 * 5 + d2;
}
__device__ __forceinline__ float2 cmul(float2 a, float2 b) {
    return make_float2(a.x * b.x - a.y * b.y, a.x * b.y + a.y * b.x);
}

// ---------------------------------------------------------------------------
// Fused: count-sketch scatter -> forward FFT(p0 + i p1) -> spectrum separation
// and pointwise product -> inverse FFT -> z  (one block per batch row)
//
// N = 16000 = 125 * 128.  Storage slot addr(n1, n2) = n1 + 125*n2.
// Forward: x[n] (n = n1 + 125*n2) scattered to rev5(n1) + 125*rev7(n2);
//   radix-2 DIT over n2 (stride 125) -> natural k2;
//   twiddle W_N^{n1*k2};
//   radix-5 DIT over n1 (stride 1)  -> natural k1;
//   F[k], k = k2 + 128*k1, lives at slot (k>>7) + 125*(k&127).
// Inverse (DIF both dims, + sign twiddles) ends with z[n] at the same
// permuted address map used at scatter. Scale 1/N at the store.
// ---------------------------------------------------------------------------
__global__ void __launch_bounds__(TPB, 1) fftconv_kernel(
    const float* __restrict__ x0, const float* __restrict__ x1,
    const int* __restrict__ h0, const int* __restrict__ h1,
    const int* __restrict__ s0, const int* __restrict__ s1)
{
    extern __shared__ float2 sh[];  // 16000 complex = 128000 B
    const int b = blockIdx.x, tid = threadIdx.x;
    const float TWOPI = 6.2831853071795864f;

    // zero
    for (int i = tid; i < NFFT; i += TPB) sh[i] = make_float2(0.f, 0.f);
    __syncthreads();

    // scatter count sketches (p0 -> re, p1 -> im), pre-permuted addresses
    for (int i = tid; i < DIN; i += TPB) {
        int bin = h0[i];
        float v = x0[b * DIN + i] * (float)(2 * s0[i] - 1);
        int addr = rev5(bin % 125) + 125 * rev7(bin / 125);
        atomicAdd(&sh[addr].x, v);
        bin = h1[i];
        v = x1[b * DIN + i] * (float)(2 * s1[i] - 1);
        addr = rev5(bin % 125) + 125 * rev7(bin / 125);
        atomicAdd(&sh[addr].y, v);
    }
    __syncthreads();

    // ---- forward radix-2 DIT over n2 dimension (stride 125), 7 stages ----
    for (int len = 2; len <= 128; len <<= 1) {
        int half = len >> 1;
        for (int t = tid; t < 8000; t += TPB) {
            int col = t % 125, bf = t / 125;
            int g = bf / half, pos = bf - g * half;
            int ia = col + 125 * (g * len + pos);
            int ib = ia + 125 * half;
            float sn, cs;
            sincosf(-TWOPI * pos / len, &sn, &cs);
            float2 A = sh[ia], B = sh[ib];
            float tr = B.x * cs - B.y * sn;
            float ti = B.x * sn + B.y * cs;
            sh[ia] = make_float2(A.x + tr, A.y + ti);
            sh[ib] = make_float2(A.x - tr, A.y - ti);
        }
        __syncthreads();
    }

    // ---- forward mid twiddle W_N^{n1*k2} ----
    for (int idx = tid; idx < NFFT; idx += TPB) {
        int n1 = rev5(idx % 125), k2 = idx / 125;
        float sn, cs;
        sincosf(-TWOPI * (float)(n1 * k2) / 16000.f, &sn, &cs);
        sh[idx] = cmul(sh[idx], make_float2(cs, sn));
    }
    __syncthreads();

    // 5-point DFT constants: forward W5f[r] = (cos(2pi r/5), -sin(2pi r/5))
    const float W5c[5] = {1.f, 0.30901699f, -0.80901699f, -0.80901699f, 0.30901699f};
    const float W5sF[5] = {0.f, -0.95105652f, -0.58778525f, 0.58778525f, 0.95105652f};
    const float W5sI[5] = {0.f,  0.95105652f,  0.58778525f, -0.58778525f, -0.95105652f};

    // ---- forward radix-5 DIT over n1 dimension (stride 1), 3 stages ----
    for (int len = 5; len <= 125; len *= 5) {
        int span = len / 5;
        for (int t = tid; t < 3200; t += TPB) {
            int k2 = t & 127, bf = t >> 7;
            int g = bf / span, pos = bf - g * span;
            int base = 125 * k2 + g * len + pos;
            float2 a[5];
#pragma unroll
            for (int q = 0; q < 5; q++) a[q] = sh[base + q * span];
#pragma unroll
            for (int t5 = 1; t5 < 5; t5++) {
                float sn, cs;
                sincosf(-TWOPI * pos * t5 / len, &sn, &cs);
                a[t5] = cmul(a[t5], make_float2(cs, sn));
            }
#pragma unroll
            for (int q = 0; q < 5; q++) {
                float2 o = a[0];
#pragma unroll
                for (int t5 = 1; t5 < 5; t5++) {
                    int r = (q * t5) % 5;
                    o.x += a[t5].x * W5c[r] - a[t5].y * W5sF[r];
                    o.y += a[t5].x * W5sF[r] + a[t5].y * W5c[r];
                }
                sh[base + q * span] = o;
            }
        }
        __syncthreads();
    }

    // ---- pointwise: separate P0/P1 from packed spectrum, Z = P0*P1 ----
    for (int k = tid; k <= 8000; k += TPB) {
        int kc = (k == 0) ? 0 : (NFFT - k);
        int sA = (k >> 7) + 125 * (k & 127);
        int sB = (kc >> 7) + 125 * (kc & 127);
        float2 FA = sh[sA], FB = sh[sB];
        float p0r = 0.5f * (FA.x + FB.x), p0i = 0.5f * (FA.y - FB.y);
        float p1r = 0.5f * (FA.y + FB.y), p1i = 0.5f * (FB.x - FA.x);
        float zr = p0r * p1r - p0i * p1i;
        float zi = p0r * p1i + p0i * p1r;
        sh[sA] = make_float2(zr, zi);
        if (sB != sA) sh[sB] = make_float2(zr, -zi);
    }
    __syncthreads();

    // ---- inverse radix-5 DIF over k1 dimension (stride 1), 3 stages ----
    for (int len = 125; len >= 5; len /= 5) {
        int span = len / 5;
        for (int t = tid; t < 3200; t += TPB) {
            int k2 = t & 127, bf = t >> 7;
            int g = bf / span, pos = bf - g * span;
            int base = 125 * k2 + g * len + pos;
            float2 a[5];
#pragma unroll
            for (int q = 0; q < 5; q++) a[q] = sh[base + q * span];
#pragma unroll
            for (int q = 0; q < 5; q++) {
                float2 o = a[0];
#pragma unroll
                for (int t5 = 1; t5 < 5; t5++) {
                    int r = (q * t5) % 5;
                    o.x += a[t5].x * W5c[r] - a[t5].y * W5sI[r];
                    o.y += a[t5].x * W5sI[r] + a[t5].y * W5c[r];
                }
                float sn, cs;
                sincosf(TWOPI * pos * q / len, &sn, &cs);
                sh[base + q * span] = cmul(o, make_float2(cs, sn));
            }
        }
        __syncthreads();
    }

    // ---- inverse mid twiddle W_N^{-n1*k2} -> e^{+2pi i n1 k2 / N} ----
    for (int idx = tid; idx < NFFT; idx += TPB) {
        int n1 = rev5(idx % 125), k2 = idx / 125;
        float sn, cs;
        sincosf(TWOPI * (float)(n1 * k2) / 16000.f, &sn, &cs);
        sh[idx] = cmul(sh[idx], make_float2(cs, sn));
    }
    __syncthreads();

    // ---- inverse radix-2 DIF over k2 dimension (stride 125), 7 stages ----
    for (int len = 128; len >= 2; len >>= 1) {
        int half = len >> 1;
        for (int t = tid; t < 8000; t += TPB) {
            int col = t % 125, bf = t / 125;
            int g = bf / half, pos = bf - g * half;
            int ia = col + 125 * (g * len + pos);
            int ib = ia + 125 * half;
            float2 A = sh[ia], B = sh[ib];
            float2 sum = make_float2(A.x + B.x, A.y + B.y);
            float2 dif = make_float2(A.x - B.x, A.y - B.y);
            float sn, cs;
            sincosf(TWOPI * pos / len, &sn, &cs);
            sh[ia] = sum;
            sh[ib] = cmul(dif, make_float2(cs, sn));
        }
        __syncthreads();
    }

    // ---- store z (real part), unpermute, scale by 1/N ----
    for (int n = tid; n < NFFT; n += TPB) {
        int addr = rev5(n % 125) + 125 * rev7(n / 125);
        g_z[b * (size_t)NFFT + n] = sh[addr].x * (1.f / 16000.f);
    }
}

// ---------------------------------------------------------------------------
// GEMM: out[1024,3000] = relu(z[1024,16000] @ W[3000,16000]^T + b)
// fp32 SIMT with packed fma.rn.f32x2 (FFMA2). 128x64x16 tiles, 8x4 micro.
// ---------------------------------------------------------------------------
#define BM 128
#define BN 64
#define BK 16

__device__ __forceinline__ unsigned long long pk2(float x, float y) {
    unsigned long long r;
    asm("mov.b64 %0, {%1, %2};" : "=l"(r) : "f"(x), "f"(y));
    return r;
}
__device__ __forceinline__ float2 upk2(unsigned long long v) {
    float2 r;
    asm("mov.b64 {%0, %1}, %2;" : "=f"(r.x), "=f"(r.y) : "l"(v));
    return r;
}
#define FMA2(d, a, bb) asm("fma.rn.f32x2 %0, %1, %2, %3;" : "=l"(d) : "l"(a), "l"(bb), "l"(d))

__global__ void __launch_bounds__(256) gemm_bias_relu(
    const float* __restrict__ Wt, const float* __restrict__ bias,
    float* __restrict__ out)
{
    __shared__ float As[BK][BM];
    __shared__ float Bs[BK][BN];
    int bx = blockIdx.x, by = blockIdx.y, tid = threadIdx.x;
    int tm = tid >> 4, tn = tid & 15;

    unsigned long long acc[8][2];
#pragma unroll
    for (int i = 0; i < 8; i++) { acc[i][0] = 0ull; acc[i][1] = 0ull; }

    int ra = tid >> 1;            // 0..127 : A row
    int ka = (tid & 1) * 8;       // k offset in A load
    int rb = tid >> 2;            // 0..63  : B row
    int kb4 = (tid & 3) * 4;      // k offset in B load
    int nW = bx * BN + rb;
    const float* zA = g_z + (by * BM + ra) * (size_t)NFFT + ka;
    const float* wB = Wt + (size_t)nW * NFFT + kb4;
    bool wok = nW < OUTN;

    for (int kb = 0; kb < NFFT; kb += BK) {
        float4 v0 = *(const float4*)(zA + kb);
        float4 v1 = *(const float4*)(zA + kb + 4);
        float4 w4 = wok ? *(const float4*)(wB + kb) : make_float4(0.f, 0.f, 0.f, 0.f);
        As[ka + 0][ra] = v0.x; As[ka + 1][ra] = v0.y;
        As[ka + 2][ra] = v0.z; As[ka + 3][ra] = v0.w;
        As[ka + 4][ra] = v1.x; As[ka + 5][ra] = v1.y;
        As[ka + 6][ra] = v1.z; As[ka + 7][ra] = v1.w;
        Bs[kb4 + 0][rb] = w4.x; Bs[kb4 + 1][rb] = w4.y;
        Bs[kb4 + 2][rb] = w4.z; Bs[kb4 + 3][rb] = w4.w;
        __syncthreads();
#pragma unroll
        for (int k = 0; k < BK; k++) {
            float4 a0 = *(const float4*)&As[k][tm * 8];
            float4 a1 = *(const float4*)&As[k][tm * 8 + 4];
            float4 bv = *(const float4*)&Bs[k][tn * 4];
            unsigned long long b01 = pk2(bv.x, bv.y);
            unsigned long long b23 = pk2(bv.z, bv.w);
            float am[8] = {a0.x, a0.y, a0.z, a0.w, a1.x, a1.y, a1.z, a1.w};
#pragma unroll
            for (int mi = 0; mi < 8; mi++) {
                unsigned long long a2 = pk2(am[mi], am[mi]);
                FMA2(acc[mi][0], a2, b01);
                FMA2(acc[mi][1], a2, b23);
            }
        }
        __syncthreads();
    }

    int n0 = bx * BN + tn * 4;
#pragma unroll
    for (int mi = 0; mi < 8; mi++) {
        int m = by * BM + tm * 8 + mi;
        float2 v01 = upk2(acc[mi][0]);
        float2 v23 = upk2(acc[mi][1]);
        float vals[4] = {v01.x, v01.y, v23.x, v23.y};
#pragma unroll
        for (int nj = 0; nj < 4; nj++) {
            int n = n0 + nj;
            if (n < OUTN) out[m * OUTN + n] = fmaxf(vals[nj] + bias[n], 0.f);
        }
    }
}

extern "C" void kernel_launch(void* const* d_in, const int* in_sizes, int n_in,
                              void* d_out, int out_size)
{
    const float* x0 = (const float*)d_in[0];
    const float* x1 = (const float*)d_in[1];
    const int* h0 = (const int*)d_in[2];
    const int* h1 = (const int*)d_in[3];
    const int* s0 = (const int*)d_in[4];
    const int* s1 = (const int*)d_in[5];
    const float* W = (const float*)d_in[6];
    const float* bias = (const float*)d_in[7];
    float* out = (float*)d_out;

    cudaFuncSetAttribute(fftconv_kernel,
                         cudaFuncAttributeMaxDynamicSharedMemorySize, NFFT * 8);
    fftconv_kernel<<<BATCH, TPB, NFFT * 8>>>(x0, x1, h0, h1, s0, s1);
    gemm_bias_relu<<<dim3((OUTN + BN - 1) / BN, BATCH / BM), 256>>>(W, bias, out);
}

// round 9
// speedup vs baseline: 2.7132x; 2.7132x over previous
#include <cuda_runtime.h>
#include <cuda_bf16.h>
#include <math.h>
#include <stdint.h>

#define NFFT  16000
#define DIN   2048
#define BATCH 1024
#define OUTN  3000
#define OUTP  3072
#define TPB   512

// ---------------- device globals (no runtime allocation) ----------------
__device__ float2 g_tw[NFFT];                          // W_16000^t = (cos, -sin)
__device__ __nv_bfloat16 g_zhi[BATCH * (size_t)NFFT];
__device__ __nv_bfloat16 g_zlo[BATCH * (size_t)NFFT];
__device__ __nv_bfloat16 g_whi[OUTP * (size_t)NFFT];
__device__ __nv_bfloat16 g_wlo[OUTP * (size_t)NFFT];

// ---------------- helpers ----------------
__device__ __forceinline__ uint32_t smem_u32(const void* p) {
    uint32_t a;
    asm("{ .reg .u64 t; cvta.to.shared.u64 t, %1; cvt.u32.u64 %0, t; }" : "=r"(a) : "l"(p));
    return a;
}
__device__ __forceinline__ int rev7(int x) { return (int)(__brev((unsigned)x) >> 25); }
__device__ __forceinline__ int rev5(int n) {
    int d0 = n % 5; n /= 5; int d1 = n % 5; int d2 = n / 5;
    return d0 * 25 + d1 * 5 + d2;
}
__device__ __forceinline__ float2 cmul(float2 a, float2 b) {
    return make_float2(a.x * b.x - a.y * b.y, a.x * b.y + a.y * b.x);
}

// ---------------- portable tensor-core / async-copy PTX (sm_80+) ----------------
#define CP_ASYNC16(dst, src) \
    asm volatile("cp.async.cg.shared.global [%0], [%1], 16;" :: "r"(dst), "l"(src))
#define CP_COMMIT() asm volatile("cp.async.commit_group;" ::: "memory")
#define CP_WAIT1()  asm volatile("cp.async.wait_group 1;" ::: "memory")

__device__ __forceinline__ void ldmx4(uint32_t* r, uint32_t addr) {
    asm volatile("ldmatrix.sync.aligned.m8n8.x4.shared.b16 {%0,%1,%2,%3}, [%4];"
        : "=r"(r[0]), "=r"(r[1]), "=r"(r[2]), "=r"(r[3]) : "r"(addr));
}
__device__ __forceinline__ void mma_bf16(float* d, const uint32_t* a, const uint32_t* b) {
    asm volatile(
        "mma.sync.aligned.m16n8k16.row.col.f32.bf16.bf16.f32 "
        "{%0,%1,%2,%3}, {%4,%5,%6,%7}, {%8,%9}, {%0,%1,%2,%3};"
        : "+f"(d[0]), "+f"(d[1]), "+f"(d[2]), "+f"(d[3])
        : "r"(a[0]), "r"(a[1]), "r"(a[2]), "r"(a[3]), "r"(b[0]), "r"(b[1]));
}

// ---------------------------------------------------------------------------
// twiddle table init: g_tw[t] = exp(-2 pi i t / 16000)
// ---------------------------------------------------------------------------
__global__ void twinit_kernel() {
    int t = blockIdx.x * blockDim.x + threadIdx.x;
    if (t < NFFT) {
        double s, c;
        sincospi(-(double)t / 8000.0, &s, &c);
        g_tw[t] = make_float2((float)c, (float)s);
    }
}

// ---------------------------------------------------------------------------
// W -> bf16 hi/lo split, padded to OUTP rows (pad rows = 0)
// ---------------------------------------------------------------------------
__global__ void wconv_kernel(const float* __restrict__ W) {
    int row = blockIdx.x;
    const float4* src = (const float4*)(W + (size_t)row * NFFT);
    uint2* dhi = (uint2*)(g_whi + (size_t)row * NFFT);
    uint2* dlo = (uint2*)(g_wlo + (size_t)row * NFFT);
    bool ok = row < OUTN;
    for (int c4 = threadIdx.x; c4 < NFFT / 4; c4 += blockDim.x) {
        float4 v = ok ? __ldg(src + c4) : make_float4(0.f, 0.f, 0.f, 0.f);
        float vv[4] = {v.x, v.y, v.z, v.w};
        unsigned short h[4], l[4];
#pragma unroll
        for (int i = 0; i < 4; i++) {
            __nv_bfloat16 hb = __float2bfloat16(vv[i]);
            __nv_bfloat16 lb = __float2bfloat16(vv[i] - __bfloat162float(hb));
            h[i] = __bfloat16_as_ushort(hb);
            l[i] = __bfloat16_as_ushort(lb);
        }
        uint2 hp, lp;
        hp.x = (uint32_t)h[0] | ((uint32_t)h[1] << 16);
        hp.y = (uint32_t)h[2] | ((uint32_t)h[3] << 16);
        lp.x = (uint32_t)l[0] | ((uint32_t)l[1] << 16);
        lp.y = (uint32_t)l[2] | ((uint32_t)l[3] << 16);
        dhi[c4] = hp;
        dlo[c4] = lp;
    }
}

// ---------------------------------------------------------------------------
// Fused count-sketch + forward FFT(p0 + i p1) + pointwise product + inverse FFT
// (table-driven twiddles). One block per batch row. Output: z as bf16 hi/lo.
// ---------------------------------------------------------------------------
__global__ void __launch_bounds__(TPB, 1) fftconv_kernel(
    const float* __restrict__ x0, const float* __restrict__ x1,
    const int* __restrict__ h0, const int* __restrict__ h1,
    const int* __restrict__ s0, const int* __restrict__ s1)
{
    extern __shared__ float2 sh[];  // 16000 complex = 128000 B
    const int b = blockIdx.x, tid = threadIdx.x;

    for (int i = tid; i < NFFT; i += TPB) sh[i] = make_float2(0.f, 0.f);
    __syncthreads();

    for (int i = tid; i < DIN; i += TPB) {
        int bin = h0[i];
        float v = x0[b * DIN + i] * (float)(2 * s0[i] - 1);
        int addr = rev5(bin % 125) + 125 * rev7(bin / 125);
        atomicAdd(&sh[addr].x, v);
        bin = h1[i];
        v = x1[b * DIN + i] * (float)(2 * s1[i] - 1);
        addr = rev5(bin % 125) + 125 * rev7(bin / 125);
        atomicAdd(&sh[addr].y, v);
    }
    __syncthreads();

    // forward radix-2 DIT over n2 (stride 125)
    for (int len = 2; len <= 128; len <<= 1) {
        int half = len >> 1, step = NFFT / len;
        for (int t = tid; t < 8000; t += TPB) {
            int col = t % 125, bf = t / 125;
            int g = bf / half, pos = bf - g * half;
            int ia = col + 125 * (g * len + pos);
            int ib = ia + 125 * half;
            float2 w = __ldg(&g_tw[pos * step]);
            float2 A = sh[ia], B = sh[ib];
            float tr = B.x * w.x - B.y * w.y;
            float ti = B.x * w.y + B.y * w.x;
            sh[ia] = make_float2(A.x + tr, A.y + ti);
            sh[ib] = make_float2(A.x - tr, A.y - ti);
        }
        __syncthreads();
    }

    // forward mid twiddle W_N^{n1*k2}
    for (int idx = tid; idx < NFFT; idx += TPB) {
        int n1 = rev5(idx % 125), k2 = idx / 125;
        float2 w = __ldg(&g_tw[n1 * k2]);
        sh[idx] = cmul(sh[idx], w);
    }
    __syncthreads();

    const float W5c[5]  = {1.f, 0.30901699f, -0.80901699f, -0.80901699f, 0.30901699f};
    const float W5sF[5] = {0.f, -0.95105652f, -0.58778525f, 0.58778525f, 0.95105652f};
    const float W5sI[5] = {0.f,  0.95105652f,  0.58778525f, -0.58778525f, -0.95105652f};

    // forward radix-5 DIT over n1 (stride 1)
    for (int len = 5; len <= 125; len *= 5) {
        int span = len / 5, step = NFFT / len;
        for (int t = tid; t < 3200; t += TPB) {
            int k2 = t & 127, bf = t >> 7;
            int g = bf / span, pos = bf - g * span;
            int base = 125 * k2 + g * len + pos;
            float2 a[5];
#pragma unroll
            for (int q = 0; q < 5; q++) a[q] = sh[base + q * span];
#pragma unroll
            for (int t5 = 1; t5 < 5; t5++) {
                float2 w = __ldg(&g_tw[pos * t5 * step]);
                a[t5] = cmul(a[t5], w);
            }
#pragma unroll
            for (int q = 0; q < 5; q++) {
                float2 o = a[0];
#pragma unroll
                for (int t5 = 1; t5 < 5; t5++) {
                    int r = (q * t5) % 5;
                    o.x += a[t5].x * W5c[r] - a[t5].y * W5sF[r];
                    o.y += a[t5].x * W5sF[r] + a[t5].y * W5c[r];
                }
                sh[base + q * span] = o;
            }
        }
        __syncthreads();
    }

    // pointwise: separate P0/P1, Z = P0*P1, Hermitian fill
    for (int k = tid; k <= 8000; k += TPB) {
        int kc = (k == 0) ? 0 : (NFFT - k);
        int sA = (k >> 7) + 125 * (k & 127);
        int sB = (kc >> 7) + 125 * (kc & 127);
        float2 FA = sh[sA], FB = sh[sB];
        float p0r = 0.5f * (FA.x + FB.x), p0i = 0.5f * (FA.y - FB.y);
        float p1r = 0.5f * (FA.y + FB.y), p1i = 0.5f * (FB.x - FA.x);
        float zr = p0r * p1r - p0i * p1i;
        float zi = p0r * p1i + p0i * p1r;
        sh[sA] = make_float2(zr, zi);
        if (sB != sA) sh[sB] = make_float2(zr, -zi);
    }
    __syncthreads();

    // inverse radix-5 DIF over k1 (stride 1)
    for (int len = 125; len >= 5; len /= 5) {
        int span = len / 5, step = NFFT / len;
        for (int t = tid; t < 3200; t += TPB) {
            int k2 = t & 127, bf = t >> 7;
            int g = bf / span, pos = bf - g * span;
            int base = 125 * k2 + g * len + pos;
            float2 a[5];
#pragma unroll
            for (int q = 0; q < 5; q++) a[q] = sh[base + q * span];
#pragma unroll
            for (int q = 0; q < 5; q++) {
                float2 o = a[0];
#pragma unroll
                for (int t5 = 1; t5 < 5; t5++) {
                    int r = (q * t5) % 5;
                    o.x += a[t5].x * W5c[r] - a[t5].y * W5sI[r];
                    o.y += a[t5].x * W5sI[r] + a[t5].y * W5c[r];
                }
                float2 w = __ldg(&g_tw[pos * q * step]);
                w.y = -w.y;
                sh[base + q * span] = cmul(o, w);
            }
        }
        __syncthreads();
    }

    // inverse mid twiddle (conjugate)
    for (int idx = tid; idx < NFFT; idx += TPB) {
        int n1 = rev5(idx % 125), k2 = idx / 125;
        float2 w = __ldg(&g_tw[n1 * k2]);
        w.y = -w.y;
        sh[idx] = cmul(sh[idx], w);
    }
    __syncthreads();

    // inverse radix-2 DIF over k2 (stride 125)
    for (int len = 128; len >= 2; len >>= 1) {
        int half = len >> 1, step = NFFT / len;
        for (int t = tid; t < 8000; t += TPB) {
            int col = t % 125, bf = t / 125;
            int g = bf / half, pos = bf - g * half;
            int ia = col + 125 * (g * len + pos);
            int ib = ia + 125 * half;
            float2 A = sh[ia], B = sh[ib];
            float2 sum = make_float2(A.x + B.x, A.y + B.y);
            float2 dif = make_float2(A.x - B.x, A.y - B.y);
            float2 w = __ldg(&g_tw[pos * step]);
            w.y = -w.y;
            sh[ia] = sum;
            sh[ib] = cmul(dif, w);
        }
        __syncthreads();
    }

    // store z as bf16 hi/lo, unpermute, scale 1/N
    for (int n = tid; n < NFFT; n += TPB) {
        int addr = rev5(n % 125) + 125 * rev7(n / 125);
        float zr = sh[addr].x * (1.f / 16000.f);
        __nv_bfloat16 hb = __float2bfloat16(zr);
        g_zhi[b * (size_t)NFFT + n] = hb;
        g_zlo[b * (size_t)NFFT + n] = __float2bfloat16(zr - __bfloat162float(hb));
    }
}

// ---------------------------------------------------------------------------
// GEMM via mma.sync (HMMA, portable PTX): out = relu(z @ W^T + b)
// bf16 split precision, 3 passes (hi*hi + lo*hi + hi*lo), fp32 accumulate.
// CTA tile 128x192, K-chunk 64, cp.async double buffering. Grid 16x8 = 128
// CTAs = one uniform wave on 148 SMs.
// ---------------------------------------------------------------------------
#define GBM 128
#define GBN 192
#define GBK 64
#define GT  256
#define LDA 144                       // smem row pitch bytes (64 bf16 + 8 pad)
#define A_TILE (GBM * LDA)            // 18432
#define B_TILE (GBN * LDA)            // 27648
#define OFF_ALO  A_TILE
#define OFF_BHI  (2 * A_TILE)
#define OFF_BLO  (2 * A_TILE + B_TILE)
#define ST_STRIDE (2 * A_TILE + 2 * B_TILE)   // 92160
#define GSMEM_TOTAL (2 * ST_STRIDE)           // 184320

__device__ __forceinline__ void load_chunk(
    uint32_t sbase, const char* Ah, const char* Al,
    const char* Bh, const char* Bl, int kb, int tid)
{
#pragma unroll
    for (int j = 0; j < 4; j++) {           // A: 128 rows x 8 units
        int u = tid + j * GT;
        int row = u >> 3, c = u & 7;
        size_t g = ((size_t)row * NFFT + kb + c * 8) * 2;
        uint32_t so = sbase + row * LDA + c * 16;
        CP_ASYNC16(so, Ah + g);
        CP_ASYNC16(so + OFF_ALO, Al + g);
    }
#pragma unroll
    for (int j = 0; j < 6; j++) {           // B: 192 rows x 8 units
        int u = tid + j * GT;
        int row = u >> 3, c = u & 7;
        size_t g = ((size_t)row * NFFT + kb + c * 8) * 2;
        uint32_t so = sbase + OFF_BHI + row * LDA + c * 16;
        CP_ASYNC16(so, Bh + g);
        CP_ASYNC16(so + B_TILE, Bl + g);
    }
}

__global__ void __launch_bounds__(GT, 1) gemm_mma_kernel(
    const float* __restrict__ bias, float* __restrict__ out)
{
    extern __shared__ char smem[];
    const uint32_t sb = smem_u32(smem);
    const int tid = threadIdx.x, wid = tid >> 5, lid = tid & 31;
    const int warp_m = wid & 1, warp_n = wid >> 1;   // 2 x 4 warps
    const int Nbase = blockIdx.x * GBN, Mbase = blockIdx.y * GBM;

    const char* Ah = (const char*)(g_zhi + (size_t)Mbase * NFFT);
    const char* Al = (const char*)(g_zlo + (size_t)Mbase * NFFT);
    const char* Bh = (const char*)(g_whi + (size_t)Nbase * NFFT);
    const char* Bl = (const char*)(g_wlo + (size_t)Nbase * NFFT);

    float acc[4][6][4];
#pragma unroll
    for (int i = 0; i < 4; i++)
#pragma unroll
        for (int j = 0; j < 6; j++)
#pragma unroll
            for (int q = 0; q < 4; q++) acc[i][j][q] = 0.f;

    // per-lane ldmatrix address components
    const int a_row = warp_m * 64 + (lid & 7) + ((lid >> 3) & 1) * 8;  // + mi*16
    const int a_col = ((lid >> 4) & 1) * 16;                            // + ks*32
    const int b_row = warp_n * 48 + ((lid >> 4) & 1) * 8 + (lid & 7);   // + ng*16
    const int b_col = ((lid >> 3) & 1) * 16;                            // + ks*32

    load_chunk(sb, Ah, Al, Bh, Bl, 0, tid);
    CP_COMMIT();

    const int NIT = NFFT / GBK;  // 250
    for (int it = 0; it < NIT; ++it) {
        if (it + 1 < NIT) {
            load_chunk(sb + ((it + 1) & 1) * ST_STRIDE, Ah, Al, Bh, Bl,
                       (it + 1) * GBK, tid);
            CP_COMMIT();
        }
        CP_WAIT1();
        __syncthreads();

        const uint32_t ab = sb + (it & 1) * ST_STRIDE;
#pragma unroll
        for (int ks = 0; ks < 4; ks++) {
            uint32_t ah[4][4], al[4][4], bh[3][4], blo[3][4];
#pragma unroll
            for (int mi = 0; mi < 4; mi++) {
                uint32_t ad = ab + (a_row + mi * 16) * LDA + ks * 32 + a_col;
                ldmx4(ah[mi], ad);
                ldmx4(al[mi], ad + OFF_ALO);
            }
#pragma unroll
            for (int ng = 0; ng < 3; ng++) {
                uint32_t bd = ab + OFF_BHI + (b_row + ng * 16) * LDA + ks * 32 + b_col;
                ldmx4(bh[ng], bd);
                ldmx4(blo[ng], bd + B_TILE);
            }
#pragma unroll
            for (int mi = 0; mi < 4; mi++)
#pragma unroll
                for (int ng = 0; ng < 3; ng++)
#pragma unroll
                    for (int h = 0; h < 2; h++) {
                        float* d = acc[mi][ng * 2 + h];
                        mma_bf16(d, ah[mi], &bh[ng][h * 2]);   // hi*hi
                        mma_bf16(d, al[mi], &bh[ng][h * 2]);   // lo*hi
                        mma_bf16(d, ah[mi], &blo[ng][h * 2]);  // hi*lo
                    }
        }
        __syncthreads();
    }

    // epilogue: bias + relu, fp32 stores (n-tiles fully in/out: 3000 % 8 == 0)
    const int r = lid >> 2, cq = (lid & 3) * 2;
#pragma unroll
    for (int mi = 0; mi < 4; mi++) {
        int m0 = Mbase + warp_m * 64 + mi * 16 + r;
#pragma unroll
        for (int nt = 0; nt < 6; nt++) {
            int n = Nbase + warp_n * 48 + nt * 8 + cq;
            if (n < OUTN) {
                float b0 = __ldg(bias + n), b1 = __ldg(bias + n + 1);
                float2 v0 = make_float2(fmaxf(acc[mi][nt][0] + b0, 0.f),
                                        fmaxf(acc[mi][nt][1] + b1, 0.f));
                float2 v1 = make_float2(fmaxf(acc[mi][nt][2] + b0, 0.f),
                                        fmaxf(acc[mi][nt][3] + b1, 0.f));
                *(float2*)(out + (size_t)m0 * OUTN + n) = v0;
                *(float2*)(out + (size_t)(m0 + 8) * OUTN + n) = v1;
            }
        }
    }
}

// ---------------------------------------------------------------------------
extern "C" void kernel_launch(void* const* d_in, const int* in_sizes, int n_in,
                              void* d_out, int out_size)
{
    const float* x0 = (const float*)d_in[0];
    const float* x1 = (const float*)d_in[1];
    const int* h0 = (const int*)d_in[2];
    const int* h1 = (const int*)d_in[3];
    const int* s0 = (const int*)d_in[4];
    const int* s1 = (const int*)d_in[5];
    const float* W = (const float*)d_in[6];
    const float* bias = (const float*)d_in[7];
    float* out = (float*)d_out;

    twinit_kernel<<<(NFFT + 255) / 256, 256>>>();
    wconv_kernel<<<OUTP, 256>>>(W);

    cudaFuncSetAttribute(fftconv_kernel,
                         cudaFuncAttributeMaxDynamicSharedMemorySize, NFFT * 8);
    fftconv_kernel<<<BATCH, TPB, NFFT * 8>>>(x0, x1, h0, h1, s0, s1);

    cudaFuncSetAttribute(gemm_mma_kernel,
                         cudaFuncAttributeMaxDynamicSharedMemorySize, GSMEM_TOTAL);
    gemm_mma_kernel<<<dim3(OUTP / GBN, BATCH / GBM), GT, GSMEM_TOTAL>>>(bias, out);
}